// round 2
// baseline (speedup 1.0000x reference)
#include <cuda_runtime.h>

#define NN    20000
#define DIN   768
#define NREL  8
#define NE    320000
#define NSEG  (NN * NREL)           /* 160000 composite (node, rel) segments */
#define KTOT  (NREL * DIN + DIN)    /* 6912: [mean | x] concat K dimension   */

#define BM 128
#define BN 128
#define BK 8

/* ------------------------------------------------------------------ */
/* static device scratch (no runtime allocation allowed)              */
/* ------------------------------------------------------------------ */
__device__ float g_mean[(size_t)NN * NREL * DIN];   /* ~491 MB */
__device__ float g_h[(size_t)NN * DIN];             /* ~61 MB  */
__device__ int   g_sorted_src[NE];
__device__ int   g_seg_cnt[NSEG];
__device__ int   g_seg_off[NSEG];
__device__ int   g_cursor[NSEG];
__device__ int   g_is64;

/* ------------------------------------------------------------------ */
/* dtype detection: jnp.int64 silently becomes int32 without x64.     */
/* For int64 little-endian data with values < 2^31, every odd 32-bit  */
/* word is zero. For int32 edge_type data (values 0..7), ~7/8 of the  */
/* sampled odd words are nonzero.                                     */
/* ------------------------------------------------------------------ */
__global__ void k_detect(const void* et_raw) {
    __shared__ int nz;
    if (threadIdx.x == 0) nz = 0;
    __syncthreads();
    const int* w = (const int*)et_raw;
    int cnt = 0;
    for (int i = threadIdx.x; i < 2048; i += blockDim.x)
        if (w[2 * i + 1] != 0) cnt++;
    atomicAdd(&nz, cnt);
    __syncthreads();
    if (threadIdx.x == 0) g_is64 = (nz == 0) ? 1 : 0;
}

__device__ __forceinline__ void load_edge(const void* ei, const void* et, int e,
                                          int& src, int& dst, int& r) {
    if (g_is64) {
        const long long* p = (const long long*)ei;
        src = (int)p[e];
        dst = (int)p[NE + e];
        r   = (int)((const long long*)et)[e];
    } else {
        const int* p = (const int*)ei;
        src = p[e];
        dst = p[NE + e];
        r   = ((const int*)et)[e];
    }
}

/* ------------------------------------------------------------------ */
/* CSR build: zero -> histogram -> scan -> place                      */
/* ------------------------------------------------------------------ */
__global__ void k_zero() {
    int i = blockIdx.x * blockDim.x + threadIdx.x;
    if (i < NSEG) { g_seg_cnt[i] = 0; g_cursor[i] = 0; }
}

__global__ void k_hist(const void* ei, const void* et) {
    int e = blockIdx.x * blockDim.x + threadIdx.x;
    if (e >= NE) return;
    int src, dst, r;
    load_edge(ei, et, e, src, dst, r);
    atomicAdd(&g_seg_cnt[dst * NREL + r], 1);
}

/* single-block exclusive scan over NSEG counters (latency ~tens of us,
 * amortized once per call across both layers)                         */
__global__ void k_scan() {
    __shared__ int sums[1024];
    const int CH = (NSEG + 1023) / 1024;   /* 157 */
    int t = threadIdx.x;
    int start = t * CH;
    int end   = start + CH; if (end > NSEG) end = NSEG;
    int s = 0;
    for (int i = start; i < end; i++) s += g_seg_cnt[i];
    sums[t] = s;
    __syncthreads();
    for (int d = 1; d < 1024; d <<= 1) {
        int v = (t >= d) ? sums[t - d] : 0;
        __syncthreads();
        sums[t] += v;
        __syncthreads();
    }
    int run = (t == 0) ? 0 : sums[t - 1];
    for (int i = start; i < end; i++) { g_seg_off[i] = run; run += g_seg_cnt[i]; }
}

__global__ void k_place(const void* ei, const void* et) {
    int e = blockIdx.x * blockDim.x + threadIdx.x;
    if (e >= NE) return;
    int src, dst, r;
    load_edge(ei, et, e, src, dst, r);
    int seg = dst * NREL + r;
    int pos = g_seg_off[seg] + atomicAdd(&g_cursor[seg], 1);
    g_sorted_src[pos] = src;
}

/* ------------------------------------------------------------------ */
/* segment mean: one warp per (node, rel) segment, no atomics.        */
/* xin rows (61 MB) are L2-resident; writes stream to g_mean.         */
/* ------------------------------------------------------------------ */
__global__ void k_aggregate(const float* __restrict__ xin) {
    int gw   = (blockIdx.x * blockDim.x + threadIdx.x) >> 5;
    if (gw >= NSEG) return;
    int lane = threadIdx.x & 31;
    int off  = g_seg_off[gw];
    int cnt  = g_seg_cnt[gw];

    float4 acc[6];
#pragma unroll
    for (int j = 0; j < 6; j++) acc[j] = make_float4(0.f, 0.f, 0.f, 0.f);

    for (int e = 0; e < cnt; e++) {
        const float4* row = (const float4*)(xin + (size_t)g_sorted_src[off + e] * DIN);
#pragma unroll
        for (int j = 0; j < 6; j++) {
            float4 v = row[j * 32 + lane];
            acc[j].x += v.x; acc[j].y += v.y; acc[j].z += v.z; acc[j].w += v.w;
        }
    }
    float inv = 1.0f / fmaxf((float)cnt, 1.0f);
    float4* m = (float4*)(g_mean + (size_t)gw * DIN);
#pragma unroll
    for (int j = 0; j < 6; j++) {
        float4 v = acc[j];
        v.x *= inv; v.y *= inv; v.z *= inv; v.w *= inv;
        m[j * 32 + lane] = v;
    }
}

/* ------------------------------------------------------------------ */
/* fused GEMM: out = [mean | x] @ [W ; root] + b  (optional ReLU)     */
/* M=20000, N=768, K=6912. 128x128x8 tiles, 8x8 microtile, dbl-buffer */
/* ------------------------------------------------------------------ */
__device__ __forceinline__ float4 loadA(const float* __restrict__ Ax, int row, int k) {
    if (row >= NN) return make_float4(0.f, 0.f, 0.f, 0.f);
    if (k < NREL * DIN)
        return *(const float4*)(g_mean + (size_t)row * (NREL * DIN) + k);
    return *(const float4*)(Ax + (size_t)row * DIN + (k - NREL * DIN));
}

__device__ __forceinline__ float4 loadB(const float* __restrict__ W,
                                        const float* __restrict__ root,
                                        int k, int col) {
    if (k < NREL * DIN)
        return *(const float4*)(W + (size_t)k * DIN + col);
    return *(const float4*)(root + (size_t)(k - NREL * DIN) * DIN + col);
}

__global__ __launch_bounds__(256, 2)
void k_gemm(const float* __restrict__ Ax,
            const float* __restrict__ W,
            const float* __restrict__ root,
            const float* __restrict__ bias,
            float* __restrict__ out,
            int do_relu) {
    __shared__ __align__(16) float As[2][BK][BM];
    __shared__ __align__(16) float Bs[2][BK][BN];

    int tid = threadIdx.x;
    int n0  = blockIdx.x * BN;   /* x-dim = N so concurrent blocks share A rows via L2 */
    int m0  = blockIdx.y * BM;
    int tx  = tid & 15;
    int ty  = tid >> 4;

    int aRow = tid >> 1;          /* 0..127 */
    int aCol = (tid & 1) * 4;     /* 0 or 4 */
    int bRow = tid >> 5;          /* 0..7   */
    int bCol = (tid & 31) * 4;    /* 0..124 */

    float acc[8][8];
#pragma unroll
    for (int i = 0; i < 8; i++)
#pragma unroll
        for (int j = 0; j < 8; j++) acc[i][j] = 0.f;

    /* prologue: tile k0 = 0 into buffer 0 */
    {
        float4 a = loadA(Ax, m0 + aRow, aCol);
        float4 b = loadB(W, root, bRow, n0 + bCol);
        As[0][aCol + 0][aRow] = a.x;
        As[0][aCol + 1][aRow] = a.y;
        As[0][aCol + 2][aRow] = a.z;
        As[0][aCol + 3][aRow] = a.w;
        *(float4*)&Bs[0][bRow][bCol] = b;
    }
    __syncthreads();

#define COMPUTE(B)                                                         \
    do {                                                                   \
        _Pragma("unroll")                                                  \
        for (int kk = 0; kk < BK; kk++) {                                  \
            float a[8], b[8];                                              \
            *(float4*)&a[0] = *(const float4*)&As[B][kk][ty * 8];          \
            *(float4*)&a[4] = *(const float4*)&As[B][kk][ty * 8 + 4];      \
            *(float4*)&b[0] = *(const float4*)&Bs[B][kk][tx * 8];          \
            *(float4*)&b[4] = *(const float4*)&Bs[B][kk][tx * 8 + 4];      \
            _Pragma("unroll")                                              \
            for (int i = 0; i < 8; i++)                                    \
                _Pragma("unroll")                                          \
                for (int j = 0; j < 8; j++) acc[i][j] += a[i] * b[j];      \
        }                                                                  \
    } while (0)

    int buf = 0;
    for (int k0 = BK; k0 < KTOT; k0 += BK) {
        float4 a = loadA(Ax, m0 + aRow, k0 + aCol);
        float4 b = loadB(W, root, k0 + bRow, n0 + bCol);
        COMPUTE(buf);
        int nb = buf ^ 1;
        As[nb][aCol + 0][aRow] = a.x;
        As[nb][aCol + 1][aRow] = a.y;
        As[nb][aCol + 2][aRow] = a.z;
        As[nb][aCol + 3][aRow] = a.w;
        *(float4*)&Bs[nb][bRow][bCol] = b;
        __syncthreads();
        buf = nb;
    }
    COMPUTE(buf);
#undef COMPUTE

    float bv[8];
#pragma unroll
    for (int j = 0; j < 8; j++) bv[j] = bias[n0 + tx * 8 + j];

#pragma unroll
    for (int i = 0; i < 8; i++) {
        int row = m0 + ty * 8 + i;
        if (row < NN) {
            float4 v0, v1;
            v0.x = acc[i][0] + bv[0]; v0.y = acc[i][1] + bv[1];
            v0.z = acc[i][2] + bv[2]; v0.w = acc[i][3] + bv[3];
            v1.x = acc[i][4] + bv[4]; v1.y = acc[i][5] + bv[5];
            v1.z = acc[i][6] + bv[6]; v1.w = acc[i][7] + bv[7];
            if (do_relu) {
                v0.x = fmaxf(v0.x, 0.f); v0.y = fmaxf(v0.y, 0.f);
                v0.z = fmaxf(v0.z, 0.f); v0.w = fmaxf(v0.w, 0.f);
                v1.x = fmaxf(v1.x, 0.f); v1.y = fmaxf(v1.y, 0.f);
                v1.z = fmaxf(v1.z, 0.f); v1.w = fmaxf(v1.w, 0.f);
            }
            *(float4*)&out[(size_t)row * DIN + n0 + tx * 8]     = v0;
            *(float4*)&out[(size_t)row * DIN + n0 + tx * 8 + 4] = v1;
        }
    }
}

/* ------------------------------------------------------------------ */
extern "C" void kernel_launch(void* const* d_in, const int* in_sizes, int n_in,
                              void* d_out, int out_size) {
    const float* x     = (const float*)d_in[0];
    const void*  ei    = d_in[1];
    const void*  et    = d_in[2];
    const float* W1    = (const float*)d_in[3];
    const float* root1 = (const float*)d_in[4];
    const float* b1    = (const float*)d_in[5];
    const float* W2    = (const float*)d_in[6];
    const float* root2 = (const float*)d_in[7];
    const float* b2    = (const float*)d_in[8];
    float*       out   = (float*)d_out;

    float* hbuf = nullptr;
    cudaGetSymbolAddress((void**)&hbuf, g_h);

    /* edge CSR built once, shared by both layers */
    k_detect<<<1, 256>>>(et);
    k_zero<<<(NSEG + 255) / 256, 256>>>();
    k_hist<<<(NE + 255) / 256, 256>>>(ei, et);
    k_scan<<<1, 1024>>>();
    k_place<<<(NE + 255) / 256, 256>>>(ei, et);

    dim3 gemm_grid(DIN / BN, (NN + BM - 1) / BM);   /* (6, 157) */

    /* layer 1: mean(x) -> GEMM(+ReLU) -> h */
    k_aggregate<<<NSEG / 8, 256>>>(x);
    k_gemm<<<gemm_grid, 256>>>(x, W1, root1, b1, hbuf, 1);

    /* layer 2: mean(h) -> GEMM -> out */
    k_aggregate<<<NSEG / 8, 256>>>(hbuf);
    k_gemm<<<gemm_grid, 256>>>(hbuf, W2, root2, b2, out, 0);
}

// round 4
// speedup vs baseline: 2.6003x; 2.6003x over previous
#include <cuda_runtime.h>
#include <cuda_bf16.h>

#define NN    20000
#define MPAD  20096                 /* 157 * 128 */
#define DIN   768
#define NREL  8
#define NE    320000
#define NSEG  (NN * NREL)
#define KMEAN (NREL * DIN)          /* 6144 */
#define KTOT  (KMEAN + DIN)         /* 6912 */
#define NSTG  (KTOT / 64)           /* 108 K-stages of 64 */

/* ------------------------------------------------------------------ */
/* static device scratch                                              */
/* ------------------------------------------------------------------ */
__device__ __nv_bfloat16 g_meanHi[(size_t)MPAD * KMEAN];
__device__ __nv_bfloat16 g_meanLo[(size_t)MPAD * KMEAN];
__device__ __nv_bfloat16 g_tailHi[2][(size_t)MPAD * DIN];   /* [0]=x, [1]=h */
__device__ __nv_bfloat16 g_tailLo[2][(size_t)MPAD * DIN];
__device__ __nv_bfloat16 g_BHi[2][(size_t)DIN * KTOT];      /* B^T per layer */
__device__ __nv_bfloat16 g_BLo[2][(size_t)DIN * KTOT];
__device__ float g_h[(size_t)NN * DIN];
__device__ int   g_sorted_src[NE];
__device__ int   g_seg_cnt[NSEG];
__device__ int   g_seg_off[NSEG];
__device__ int   g_cursor[NSEG];
__device__ int   g_is64;

/* ------------------------------------------------------------------ */
/* PTX helpers — all non-arch-specific (sm_80+ class)                 */
/* ------------------------------------------------------------------ */
__device__ __forceinline__ unsigned smem_u32(const void* p) {
    unsigned a;
    asm("{ .reg .u64 t; cvta.to.shared.u64 t, %1; cvt.u32.u64 %0, t; }" : "=r"(a) : "l"(p));
    return a;
}
#define CP16(dst, src) \
    asm volatile("cp.async.cg.shared.global [%0], [%1], 16;" :: "r"(dst), "l"(src))
#define CP_COMMIT() asm volatile("cp.async.commit_group;" ::: "memory")
#define CP_WAIT(n)  asm volatile("cp.async.wait_group %0;" :: "n"(n) : "memory")

#define LDSM4(R, addr)                                                       \
    asm volatile("ldmatrix.sync.aligned.m8n8.x4.shared.b16 {%0,%1,%2,%3}, [%4];" \
        : "=r"((R)[0]), "=r"((R)[1]), "=r"((R)[2]), "=r"((R)[3]) : "r"(addr))

#define MMA16816(C, A, B0, B1)                                               \
    asm volatile("mma.sync.aligned.m16n8k16.row.col.f32.bf16.bf16.f32 "      \
        "{%0,%1,%2,%3}, {%4,%5,%6,%7}, {%8,%9}, {%0,%1,%2,%3};"              \
        : "+f"((C)[0]), "+f"((C)[1]), "+f"((C)[2]), "+f"((C)[3])             \
        : "r"((A)[0]), "r"((A)[1]), "r"((A)[2]), "r"((A)[3]),                \
          "r"(B0), "r"(B1))

__device__ __forceinline__ unsigned swz(unsigned off) { return off ^ ((off >> 3) & 0x70); }

__device__ __forceinline__ void split2(float a, float b, unsigned& hi, unsigned& lo) {
    __nv_bfloat16 ha = __float2bfloat16(a);
    __nv_bfloat16 hb = __float2bfloat16(b);
    __nv_bfloat16 la = __float2bfloat16(a - __bfloat162float(ha));
    __nv_bfloat16 lb = __float2bfloat16(b - __bfloat162float(hb));
    hi = ((unsigned)__bfloat16_as_ushort(hb) << 16) | __bfloat16_as_ushort(ha);
    lo = ((unsigned)__bfloat16_as_ushort(lb) << 16) | __bfloat16_as_ushort(la);
}

/* ------------------------------------------------------------------ */
/* dtype detection + CSR build                                        */
/* ------------------------------------------------------------------ */
__global__ void k_detect(const void* et_raw) {
    __shared__ int nz;
    if (threadIdx.x == 0) nz = 0;
    __syncthreads();
    const int* w = (const int*)et_raw;
    int cnt = 0;
    for (int i = threadIdx.x; i < 2048; i += blockDim.x)
        if (w[2 * i + 1] != 0) cnt++;
    atomicAdd(&nz, cnt);
    __syncthreads();
    if (threadIdx.x == 0) g_is64 = (nz == 0) ? 1 : 0;
}

__device__ __forceinline__ void load_edge(const void* ei, const void* et, int e,
                                          int& src, int& dst, int& r) {
    if (g_is64) {
        const long long* p = (const long long*)ei;
        src = (int)p[e]; dst = (int)p[NE + e];
        r = (int)((const long long*)et)[e];
    } else {
        const int* p = (const int*)ei;
        src = p[e]; dst = p[NE + e];
        r = ((const int*)et)[e];
    }
}

__global__ void k_zero() {
    int i = blockIdx.x * blockDim.x + threadIdx.x;
    if (i < NSEG) { g_seg_cnt[i] = 0; g_cursor[i] = 0; }
}
__global__ void k_hist(const void* ei, const void* et) {
    int e = blockIdx.x * blockDim.x + threadIdx.x;
    if (e >= NE) return;
    int s, d, r; load_edge(ei, et, e, s, d, r);
    atomicAdd(&g_seg_cnt[d * NREL + r], 1);
}
__global__ void k_scan() {
    __shared__ int sums[1024];
    const int CH = (NSEG + 1023) / 1024;
    int t = threadIdx.x;
    int start = t * CH, end = start + CH; if (end > NSEG) end = NSEG;
    int s = 0;
    for (int i = start; i < end; i++) s += g_seg_cnt[i];
    sums[t] = s;
    __syncthreads();
    for (int d = 1; d < 1024; d <<= 1) {
        int v = (t >= d) ? sums[t - d] : 0;
        __syncthreads();
        sums[t] += v;
        __syncthreads();
    }
    int run = (t == 0) ? 0 : sums[t - 1];
    for (int i = start; i < end; i++) { g_seg_off[i] = run; run += g_seg_cnt[i]; }
}
__global__ void k_place(const void* ei, const void* et) {
    int e = blockIdx.x * blockDim.x + threadIdx.x;
    if (e >= NE) return;
    int s, d, r; load_edge(ei, et, e, s, d, r);
    int seg = d * NREL + r;
    g_sorted_src[g_seg_off[seg] + atomicAdd(&g_cursor[seg], 1)] = s;
}

/* ------------------------------------------------------------------ */
/* operand preparation                                                */
/* ------------------------------------------------------------------ */
__global__ void k_convW(const float* __restrict__ W, const float* __restrict__ root,
                        __nv_bfloat16* __restrict__ bhi, __nv_bfloat16* __restrict__ blo) {
    __shared__ float t[32][33];
    int tx = threadIdx.x, ty = threadIdx.y;
    int kb = blockIdx.x * 32, nb = blockIdx.y * 32;
    for (int j = ty; j < 32; j += 8) {
        int k = kb + j;
        const float* src = (k < KMEAN) ? (W + (size_t)k * DIN)
                                       : (root + (size_t)(k - KMEAN) * DIN);
        t[j][tx] = src[nb + tx];
    }
    __syncthreads();
    for (int j = ty; j < 32; j += 8) {
        int n = nb + j;
        float v = t[tx][j];
        __nv_bfloat16 h = __float2bfloat16(v);
        __nv_bfloat16 l = __float2bfloat16(v - __bfloat162float(h));
        bhi[(size_t)n * KTOT + kb + tx] = h;
        blo[(size_t)n * KTOT + kb + tx] = l;
    }
}

__global__ void k_convX(const float* __restrict__ x,
                        __nv_bfloat16* __restrict__ hi, __nv_bfloat16* __restrict__ lo) {
    int idx = blockIdx.x * blockDim.x + threadIdx.x;
    if (idx >= NN * (DIN / 4)) return;
    float4 v = ((const float4*)x)[idx];
    unsigned h0, l0, h1, l1;
    split2(v.x, v.y, h0, l0);
    split2(v.z, v.w, h1, l1);
    ((uint2*)hi)[idx] = make_uint2(h0, h1);
    ((uint2*)lo)[idx] = make_uint2(l0, l1);
}

/* segment mean -> bf16 hi/lo directly into the A mean region          */
__global__ void k_aggregate(const float* __restrict__ xin) {
    int gw = (blockIdx.x * blockDim.x + threadIdx.x) >> 5;
    if (gw >= NSEG) return;
    int lane = threadIdx.x & 31;
    int off = g_seg_off[gw], cnt = g_seg_cnt[gw];

    float4 acc[6];
#pragma unroll
    for (int j = 0; j < 6; j++) acc[j] = make_float4(0.f, 0.f, 0.f, 0.f);

    for (int e = 0; e < cnt; e++) {
        const float4* row = (const float4*)(xin + (size_t)g_sorted_src[off + e] * DIN);
#pragma unroll
        for (int j = 0; j < 6; j++) {
            float4 v = row[j * 32 + lane];
            acc[j].x += v.x; acc[j].y += v.y; acc[j].z += v.z; acc[j].w += v.w;
        }
    }
    float inv = 1.0f / fmaxf((float)cnt, 1.0f);
    uint2* mh = (uint2*)(g_meanHi + (size_t)gw * DIN);
    uint2* ml = (uint2*)(g_meanLo + (size_t)gw * DIN);
#pragma unroll
    for (int j = 0; j < 6; j++) {
        float4 v = acc[j];
        v.x *= inv; v.y *= inv; v.z *= inv; v.w *= inv;
        unsigned h0, l0, h1, l1;
        split2(v.x, v.y, h0, l0);
        split2(v.z, v.w, h1, l1);
        mh[j * 32 + lane] = make_uint2(h0, h1);
        ml[j * 32 + lane] = make_uint2(l0, l1);
    }
}

/* ------------------------------------------------------------------ */
/* split-bf16 GEMM via mma.sync: out = [mean|tail] @ B^T + b (+ReLU)  */
/* CTA 128x128, BK=64, 8 warps (2M x 4N), 3-stage cp.async pipeline   */
/* ------------------------------------------------------------------ */
#define STG_SZ   65536
#define OFF_AHI(b) ((b) * STG_SZ + 0)
#define OFF_ALO(b) ((b) * STG_SZ + 16384)
#define OFF_BHI(b) ((b) * STG_SZ + 32768)
#define OFF_BLO(b) ((b) * STG_SZ + 49152)
#define SMEM_TOTAL (3 * STG_SZ)             /* 196608 */

__global__ __launch_bounds__(256)
void k_gemm_mma(const __nv_bfloat16* __restrict__ meanHi, const __nv_bfloat16* __restrict__ meanLo,
                const __nv_bfloat16* __restrict__ tailHi, const __nv_bfloat16* __restrict__ tailLo,
                const __nv_bfloat16* __restrict__ BHi,    const __nv_bfloat16* __restrict__ BLo,
                const float* __restrict__ bias, float* __restrict__ outF,
                __nv_bfloat16* __restrict__ auxHi, __nv_bfloat16* __restrict__ auxLo,
                int do_relu, int write_aux) {
    extern __shared__ __align__(1024) char smem[];
    const int tid  = threadIdx.x;
    const int wid  = tid >> 5, lane = tid & 31;
    const int wm   = wid >> 2;          /* 0..1  : warp M tile (64 rows) */
    const int wn   = wid & 3;           /* 0..3  : warp N tile (32 cols) */
    const int n0   = blockIdx.x * 128;
    const int m0   = blockIdx.y * 128;
    const unsigned sbase = smem_u32(smem);

    float acc[4][4][4];
#pragma unroll
    for (int a = 0; a < 4; a++)
#pragma unroll
        for (int b = 0; b < 4; b++)
#pragma unroll
            for (int c = 0; c < 4; c++) acc[a][b][c] = 0.f;

    /* ---- stage loader: 16 cp.async(16B) per thread per stage ---- */
    auto issue_stage = [&](int s, int buf) {
        const int kc = s * 64;
        const __nv_bfloat16 *ah, *al;
        size_t stride; int c0;
        if (kc < KMEAN) { ah = meanHi; al = meanLo; stride = KMEAN; c0 = kc; }
        else            { ah = tailHi; al = tailLo; stride = DIN;   c0 = kc - KMEAN; }
#pragma unroll
        for (int t = 0; t < 4; t++) {
            int c   = tid + t * 256;       /* 0..1023 */
            int row = c >> 3, kg = c & 7;
            unsigned sw = swz((unsigned)(row * 128 + kg * 16));
            const char* sa = (const char*)(ah + (size_t)(m0 + row) * stride + c0) + kg * 16;
            const char* sl = (const char*)(al + (size_t)(m0 + row) * stride + c0) + kg * 16;
            const char* sb = (const char*)(BHi + (size_t)(n0 + row) * KTOT + kc) + kg * 16;
            const char* sc = (const char*)(BLo + (size_t)(n0 + row) * KTOT + kc) + kg * 16;
            CP16(sbase + OFF_AHI(buf) + sw, sa);
            CP16(sbase + OFF_ALO(buf) + sw, sl);
            CP16(sbase + OFF_BHI(buf) + sw, sb);
            CP16(sbase + OFF_BLO(buf) + sw, sc);
        }
    };

    issue_stage(0, 0); CP_COMMIT();
    issue_stage(1, 1); CP_COMMIT();
    issue_stage(2, 2); CP_COMMIT();

    const int lrow = lane & 15, lcol = lane >> 4;

    int buf = 0;
    for (int s = 0; s < NSTG; s++) {
        CP_WAIT(2);
        __syncthreads();

        unsigned baseAH = sbase + OFF_AHI(buf);
        unsigned baseAL = sbase + OFF_ALO(buf);
        unsigned baseBH = sbase + OFF_BHI(buf);
        unsigned baseBL = sbase + OFF_BLO(buf);

#pragma unroll
        for (int ks = 0; ks < 4; ks++) {
            unsigned ahf[4][4], alf[4][4], bhf[2][4], blf[2][4];
#pragma unroll
            for (int mb = 0; mb < 4; mb++) {
                unsigned off = swz((unsigned)((wm * 64 + mb * 16 + lrow) * 128
                                              + (ks * 2 + lcol) * 16));
                LDSM4(ahf[mb], baseAH + off);
                LDSM4(alf[mb], baseAL + off);
            }
#pragma unroll
            for (int p = 0; p < 2; p++) {
                unsigned off = swz((unsigned)((wn * 32 + p * 16 + lrow) * 128
                                              + (ks * 2 + lcol) * 16));
                LDSM4(bhf[p], baseBH + off);
                LDSM4(blf[p], baseBL + off);
            }
#pragma unroll
            for (int mb = 0; mb < 4; mb++)
#pragma unroll
                for (int nb = 0; nb < 4; nb++) {
                    int p = nb >> 1, q = nb & 1;
                    MMA16816(acc[mb][nb], ahf[mb], bhf[p][q], bhf[p][q + 2]);
                    MMA16816(acc[mb][nb], ahf[mb], blf[p][q], blf[p][q + 2]);
                    MMA16816(acc[mb][nb], alf[mb], bhf[p][q], bhf[p][q + 2]);
                }
        }
        __syncthreads();
        if (s + 3 < NSTG) issue_stage(s + 3, buf);
        CP_COMMIT();
        buf = (buf == 2) ? 0 : buf + 1;
    }

    /* ---- epilogue: bias (+ReLU), direct stores, optional bf16 aux ---- */
#pragma unroll
    for (int mb = 0; mb < 4; mb++) {
        int rbase = m0 + wm * 64 + mb * 16 + (lane >> 2);
#pragma unroll
        for (int nb = 0; nb < 4; nb++) {
            int col = n0 + wn * 32 + nb * 8 + (lane & 3) * 2;
            float bv0 = __ldg(&bias[col]);
            float bv1 = __ldg(&bias[col + 1]);
#pragma unroll
            for (int h = 0; h < 2; h++) {
                int row = rbase + h * 8;
                float v0 = acc[mb][nb][h * 2 + 0] + bv0;
                float v1 = acc[mb][nb][h * 2 + 1] + bv1;
                if (do_relu) { v0 = fmaxf(v0, 0.f); v1 = fmaxf(v1, 0.f); }
                if (row < NN) {
                    size_t e = (size_t)row * DIN + col;
                    *(float2*)&outF[e] = make_float2(v0, v1);
                    if (write_aux) {
                        unsigned hi, lo;
                        split2(v0, v1, hi, lo);
                        *(unsigned*)(auxHi + e) = hi;
                        *(unsigned*)(auxLo + e) = lo;
                    }
                }
            }
        }
    }
}

/* ------------------------------------------------------------------ */
extern "C" void kernel_launch(void* const* d_in, const int* in_sizes, int n_in,
                              void* d_out, int out_size) {
    const float* x     = (const float*)d_in[0];
    const void*  ei    = d_in[1];
    const void*  et    = d_in[2];
    const float* W1    = (const float*)d_in[3];
    const float* root1 = (const float*)d_in[4];
    const float* b1    = (const float*)d_in[5];
    const float* W2    = (const float*)d_in[6];
    const float* root2 = (const float*)d_in[7];
    const float* b2    = (const float*)d_in[8];
    float*       out   = (float*)d_out;

    __nv_bfloat16 *meanHi, *meanLo, *tailHi, *tailLo, *BHi, *BLo;
    float* hbuf;
    cudaGetSymbolAddress((void**)&meanHi, g_meanHi);
    cudaGetSymbolAddress((void**)&meanLo, g_meanLo);
    cudaGetSymbolAddress((void**)&tailHi, g_tailHi);
    cudaGetSymbolAddress((void**)&tailLo, g_tailLo);
    cudaGetSymbolAddress((void**)&BHi, g_BHi);
    cudaGetSymbolAddress((void**)&BLo, g_BLo);
    cudaGetSymbolAddress((void**)&hbuf, g_h);
    __nv_bfloat16* tail1Hi = tailHi + (size_t)MPAD * DIN;
    __nv_bfloat16* tail1Lo = tailLo + (size_t)MPAD * DIN;
    __nv_bfloat16* B2Hi    = BHi + (size_t)DIN * KTOT;
    __nv_bfloat16* B2Lo    = BLo + (size_t)DIN * KTOT;

    cudaFuncSetAttribute(k_gemm_mma, cudaFuncAttributeMaxDynamicSharedMemorySize, SMEM_TOTAL);

    /* CSR build (shared by both layers) */
    k_detect<<<1, 256>>>(et);
    k_zero<<<(NSEG + 255) / 256, 256>>>();
    k_hist<<<(NE + 255) / 256, 256>>>(ei, et);
    k_scan<<<1, 1024>>>();
    k_place<<<(NE + 255) / 256, 256>>>(ei, et);

    /* operand prep */
    dim3 wgrid(KTOT / 32, DIN / 32);
    k_convW<<<wgrid, dim3(32, 8)>>>(W1, root1, BHi, BLo);
    k_convW<<<wgrid, dim3(32, 8)>>>(W2, root2, B2Hi, B2Lo);
    k_convX<<<(NN * (DIN / 4) + 255) / 256, 256>>>(x, tailHi, tailLo);

    dim3 ggrid(DIN / 128, MPAD / 128);   /* (6, 157) */

    /* layer 1 */
    k_aggregate<<<NSEG / 8, 256>>>(x);
    k_gemm_mma<<<ggrid, 256, SMEM_TOTAL>>>(meanHi, meanLo, tailHi, tailLo,
                                           BHi, BLo, b1, hbuf,
                                           tail1Hi, tail1Lo, 1, 1);
    /* layer 2 */
    k_aggregate<<<NSEG / 8, 256>>>(hbuf);
    k_gemm_mma<<<ggrid, 256, SMEM_TOTAL>>>(meanHi, meanLo, tail1Hi, tail1Lo,
                                           B2Hi, B2Lo, b2, out,
                                           nullptr, nullptr, 0, 0);
}